// round 1
// baseline (speedup 1.0000x reference)
#include <cuda_runtime.h>
#include <cstddef>

#define N_NODES 100000
#define N_EDGES 3200000
#define D_IN    512
#define D_HID   512
#define D_OUT   256

// ---------------- scratch (no cudaMalloc allowed) ----------------
__device__ float g_h0[(size_t)N_NODES * D_HID];   // 204.8 MB
__device__ float g_h1[(size_t)N_NODES * D_HID];   // 204.8 MB
__device__ int   g_rptr[N_NODES + 1];
__device__ int   g_cnt[N_NODES];
__device__ int   g_cur[N_NODES];
__device__ int   g_perm[N_EDGES];

// ---------------- small helpers ----------------
__device__ __forceinline__ void fma4(float4& a, float w, const float4 v) {
    a.x = fmaf(w, v.x, a.x);
    a.y = fmaf(w, v.y, a.y);
    a.z = fmaf(w, v.z, a.z);
    a.w = fmaf(w, v.w, a.w);
}
__device__ __forceinline__ float4 relu4(float4 a) {
    a.x = fmaxf(a.x, 0.f); a.y = fmaxf(a.y, 0.f);
    a.z = fmaxf(a.z, 0.f); a.w = fmaxf(a.w, 0.f);
    return a;
}

// ---------------- CSR build ----------------
__global__ void zero_counts_kernel() {
    int i = blockIdx.x * blockDim.x + threadIdx.x;
    if (i < N_NODES) { g_cnt[i] = 0; g_cur[i] = 0; }
}

__global__ void hist_kernel(const int* __restrict__ erow) {
    int e = blockIdx.x * blockDim.x + threadIdx.x;
    if (e < N_EDGES) atomicAdd(&g_cnt[erow[e]], 1);
}

// single-block exclusive scan of g_cnt -> g_rptr (1024 threads)
__global__ void scan_kernel() {
    __shared__ int sdata[1024];
    __shared__ int s_carry;
    const int tid = threadIdx.x;
    if (tid == 0) s_carry = 0;
    __syncthreads();
    for (int base = 0; base < N_NODES; base += 1024) {
        int v = (base + tid < N_NODES) ? g_cnt[base + tid] : 0;
        sdata[tid] = v;
        __syncthreads();
        // Hillis-Steele inclusive scan
        #pragma unroll
        for (int off = 1; off < 1024; off <<= 1) {
            int t = (tid >= off) ? sdata[tid - off] : 0;
            __syncthreads();
            sdata[tid] += t;
            __syncthreads();
        }
        int incl = sdata[tid];
        if (base + tid < N_NODES) g_rptr[base + tid + 1] = s_carry + incl;
        __syncthreads();
        if (tid == 1023) s_carry += incl;
        __syncthreads();
    }
    if (tid == 0) g_rptr[0] = 0;
}

__global__ void scatter_kernel(const int* __restrict__ erow) {
    int e = blockIdx.x * blockDim.x + threadIdx.x;
    if (e < N_EDGES) {
        int r = erow[e];
        int pos = g_rptr[r] + atomicAdd(&g_cur[r], 1);
        g_perm[pos] = e;
    }
}

// make within-row order deterministic (ascending edge id): fp32 sum order is
// then identical on every graph replay despite the atomic scatter above.
__global__ void sortrows_kernel() {
    int r = blockIdx.x * blockDim.x + threadIdx.x;
    if (r >= N_NODES) return;
    int beg = g_rptr[r], end = g_rptr[r + 1];
    for (int i = beg + 1; i < end; i++) {
        int key = g_perm[i];
        int j = i - 1;
        while (j >= beg && g_perm[j] > key) { g_perm[j + 1] = g_perm[j]; j--; }
        g_perm[j + 1] = key;
    }
}

// ---------------- SpMM (+ReLU): warp per row, gather from g_h0 -> g_h1 ----
__global__ void __launch_bounds__(256) spmm_relu_kernel(
    const int* __restrict__ ecol, const float* __restrict__ eval)
{
    int gw   = (blockIdx.x * blockDim.x + threadIdx.x) >> 5;
    int lane = threadIdx.x & 31;
    if (gw >= N_NODES) return;
    int beg = g_rptr[gw], end = g_rptr[gw + 1];

    float4 acc0 = make_float4(0.f, 0.f, 0.f, 0.f);
    float4 acc1 = acc0, acc2 = acc0, acc3 = acc0;

    for (int b = beg; b < end; b += 32) {
        int n = end - b;
        if (n > 32) n = 32;
        int   c = 0;
        float w = 0.f;
        if (lane < n) {
            int id = g_perm[b + lane];
            c = ecol[id];
            w = eval[id];
        }
        for (int j = 0; j < n; j++) {
            int   cj = __shfl_sync(0xffffffffu, c, j);
            float wj = __shfl_sync(0xffffffffu, w, j);
            const float4* hr = reinterpret_cast<const float4*>(g_h0 + (size_t)cj * D_HID);
            float4 v0 = hr[lane];
            float4 v1 = hr[lane + 32];
            float4 v2 = hr[lane + 64];
            float4 v3 = hr[lane + 96];
            fma4(acc0, wj, v0);
            fma4(acc1, wj, v1);
            fma4(acc2, wj, v2);
            fma4(acc3, wj, v3);
        }
    }
    float4* o = reinterpret_cast<float4*>(g_h1 + (size_t)gw * D_HID);
    o[lane]      = relu4(acc0);
    o[lane + 32] = relu4(acc1);
    o[lane + 64] = relu4(acc2);
    o[lane + 96] = relu4(acc3);
}

// ---------------- GEMM: C[m,n] = sum_k A[m,k] * B[n,k] ----------------
// A: MxK row-major, B: NxK row-major (both K-contiguous), C: MxN row-major.
template <bool RELU>
__global__ void __launch_bounds__(256, 2) gemm_tn_kernel(
    const float* __restrict__ A, const float* __restrict__ B,
    float* __restrict__ C, int M, int N, int K)
{
    constexpr int BM = 128, BN = 128, BK = 16;
    __shared__ float As[BK][BM];
    __shared__ float Bs[BK][BN];

    const int tid = threadIdx.x;
    const int bm = blockIdx.y * BM;
    const int bn = blockIdx.x * BN;
    const int ty = tid >> 4;   // 0..15
    const int tx = tid & 15;   // 0..15

    float acc[8][8];
    #pragma unroll
    for (int i = 0; i < 8; i++)
        #pragma unroll
        for (int j = 0; j < 8; j++) acc[i][j] = 0.f;

    for (int k0 = 0; k0 < K; k0 += BK) {
        // load A tile (M-edge guarded)
        #pragma unroll
        for (int i = 0; i < 2; i++) {
            int idx = tid + i * 256;
            int r = idx >> 2;
            int cv = (idx & 3) * 4;
            float4 v = make_float4(0.f, 0.f, 0.f, 0.f);
            int gr = bm + r;
            if (gr < M) v = *reinterpret_cast<const float4*>(A + (size_t)gr * K + k0 + cv);
            As[cv + 0][r] = v.x; As[cv + 1][r] = v.y;
            As[cv + 2][r] = v.z; As[cv + 3][r] = v.w;
        }
        // load B tile (N is a multiple of 128, K a multiple of 16 -> no guard)
        #pragma unroll
        for (int i = 0; i < 2; i++) {
            int idx = tid + i * 256;
            int r = idx >> 2;
            int cv = (idx & 3) * 4;
            float4 v = *reinterpret_cast<const float4*>(B + (size_t)(bn + r) * K + k0 + cv);
            Bs[cv + 0][r] = v.x; Bs[cv + 1][r] = v.y;
            Bs[cv + 2][r] = v.z; Bs[cv + 3][r] = v.w;
        }
        __syncthreads();

        #pragma unroll
        for (int k = 0; k < BK; k++) {
            float a[8], b[8];
            *reinterpret_cast<float4*>(&a[0]) = *reinterpret_cast<const float4*>(&As[k][ty * 8]);
            *reinterpret_cast<float4*>(&a[4]) = *reinterpret_cast<const float4*>(&As[k][ty * 8 + 4]);
            *reinterpret_cast<float4*>(&b[0]) = *reinterpret_cast<const float4*>(&Bs[k][tx * 8]);
            *reinterpret_cast<float4*>(&b[4]) = *reinterpret_cast<const float4*>(&Bs[k][tx * 8 + 4]);
            #pragma unroll
            for (int i = 0; i < 8; i++)
                #pragma unroll
                for (int j = 0; j < 8; j++)
                    acc[i][j] = fmaf(a[i], b[j], acc[i][j]);
        }
        __syncthreads();
    }

    #pragma unroll
    for (int i = 0; i < 8; i++) {
        int gr = bm + ty * 8 + i;
        if (gr >= M) continue;
        float* cp = C + (size_t)gr * N + bn + tx * 8;
        float4 v0, v1;
        v0.x = acc[i][0]; v0.y = acc[i][1]; v0.z = acc[i][2]; v0.w = acc[i][3];
        v1.x = acc[i][4]; v1.y = acc[i][5]; v1.z = acc[i][6]; v1.w = acc[i][7];
        if (RELU) { v0 = relu4(v0); v1 = relu4(v1); }
        *reinterpret_cast<float4*>(cp)     = v0;
        *reinterpret_cast<float4*>(cp + 4) = v1;
    }
}

// ---------------- launch ----------------
extern "C" void kernel_launch(void* const* d_in, const int* in_sizes, int n_in,
                              void* d_out, int out_size)
{
    const float* x    = (const float*)d_in[0];
    const int*   erow = (const int*)  d_in[1];
    const int*   ecol = (const int*)  d_in[2];
    const float* eval = (const float*)d_in[3];
    const float* W0   = (const float*)d_in[4];
    const float* W1   = (const float*)d_in[5];
    const float* W2   = (const float*)d_in[6];
    float* out = (float*)d_out;

    float *h0, *h1;
    cudaGetSymbolAddress((void**)&h0, g_h0);
    cudaGetSymbolAddress((void**)&h1, g_h1);

    // CSR build (independent of GEMM0 -> issue first, same stream)
    zero_counts_kernel<<<(N_NODES + 255) / 256, 256>>>();
    hist_kernel<<<(N_EDGES + 255) / 256, 256>>>(erow);
    scan_kernel<<<1, 1024>>>();
    scatter_kernel<<<(N_EDGES + 255) / 256, 256>>>(erow);
    sortrows_kernel<<<(N_NODES + 127) / 128, 128>>>();

    // h0 = x @ W0^T
    {
        dim3 grid(D_HID / 128, (N_NODES + 127) / 128);
        gemm_tn_kernel<false><<<grid, 256>>>(x, W0, h0, N_NODES, D_HID, D_IN);
    }
    // h1 = relu(A @ h0)
    spmm_relu_kernel<<<(N_NODES * 32 + 255) / 256, 256>>>(ecol, eval);
    // h0 (reused) = relu(h1 @ W1^T)
    {
        dim3 grid(D_HID / 128, (N_NODES + 127) / 128);
        gemm_tn_kernel<true><<<grid, 256>>>(h1, W1, h0, N_NODES, D_HID, D_HID);
    }
    // out = h0 @ W2^T
    {
        dim3 grid(D_OUT / 128, (N_NODES + 127) / 128);
        gemm_tn_kernel<false><<<grid, 256>>>(h0, W2, out, N_NODES, D_OUT, D_HID);
    }
}

// round 6
// speedup vs baseline: 1.9087x; 1.9087x over previous
#include <cuda_runtime.h>
#include <cuda_bf16.h>
#include <cstdint>
#include <cstddef>

#define N_NODES 100000
#define N_EDGES 3200000
#define D_IN    512
#define D_HID   512
#define D_OUT   256

// ---------------- scratch (no cudaMalloc allowed) ----------------
__device__ float g_h0[(size_t)N_NODES * D_HID];   // 204.8 MB
__device__ float g_h1[(size_t)N_NODES * D_HID];   // 204.8 MB
__device__ int   g_rptr[N_NODES + 1];
__device__ int   g_cnt[N_NODES];
__device__ int   g_cur[N_NODES];
__device__ int   g_perm[N_EDGES];
// pre-converted weights (bf16 hi/lo split): W0 @0, W1 @262144, W2 @524288
#define W_TOTAL 655360
__device__ __nv_bfloat16 g_Whi[W_TOTAL];
__device__ __nv_bfloat16 g_Wlo[W_TOTAL];

// ---------------- helpers ----------------
__device__ __forceinline__ void fma4(float4& a, float w, const float4 v) {
    a.x = fmaf(w, v.x, a.x); a.y = fmaf(w, v.y, a.y);
    a.z = fmaf(w, v.z, a.z); a.w = fmaf(w, v.w, a.w);
}
__device__ __forceinline__ float4 relu4(float4 a) {
    a.x = fmaxf(a.x, 0.f); a.y = fmaxf(a.y, 0.f);
    a.z = fmaxf(a.z, 0.f); a.w = fmaxf(a.w, 0.f);
    return a;
}
__device__ __forceinline__ uint32_t smem_u32(const void* p) {
    uint32_t a;
    asm("{ .reg .u64 t; cvta.to.shared.u64 t, %1; cvt.u32.u64 %0, t; }" : "=r"(a) : "l"(p));
    return a;
}
__device__ __forceinline__ uint32_t pack_bf16x2(float hi_elem, float lo_elem) {
    uint32_t r;
    asm("cvt.rn.bf16x2.f32 %0, %1, %2;" : "=r"(r) : "f"(hi_elem), "f"(lo_elem));
    return r;
}
__device__ __forceinline__ void ldsm4(uint32_t* r, uint32_t addr) {
    asm volatile("ldmatrix.sync.aligned.m8n8.x4.shared.b16 {%0,%1,%2,%3}, [%4];"
                 : "=r"(r[0]), "=r"(r[1]), "=r"(r[2]), "=r"(r[3]) : "r"(addr));
}
__device__ __forceinline__ void mma16816(float* d, const uint32_t* a,
                                         uint32_t b0, uint32_t b1) {
    asm volatile(
        "mma.sync.aligned.m16n8k16.row.col.f32.bf16.bf16.f32 "
        "{%0,%1,%2,%3}, {%4,%5,%6,%7}, {%8,%9}, {%0,%1,%2,%3};"
        : "+f"(d[0]), "+f"(d[1]), "+f"(d[2]), "+f"(d[3])
        : "r"(a[0]), "r"(a[1]), "r"(a[2]), "r"(a[3]), "r"(b0), "r"(b1));
}

// ---------------- weight conversion (tiny) ----------------
__global__ void convert_w_kernel(const float* __restrict__ W0,
                                 const float* __restrict__ W1,
                                 const float* __restrict__ W2) {
    int i = blockIdx.x * blockDim.x + threadIdx.x;
    if (i >= W_TOTAL) return;
    float v = (i < 262144) ? W0[i] : (i < 524288) ? W1[i - 262144] : W2[i - 524288];
    __nv_bfloat16 h = __float2bfloat16(v);
    g_Whi[i] = h;
    g_Wlo[i] = __float2bfloat16(v - __bfloat162float(h));
}

// ---------------- CSR build ----------------
__global__ void zero_counts_kernel() {
    int i = blockIdx.x * blockDim.x + threadIdx.x;
    if (i < N_NODES) { g_cnt[i] = 0; g_cur[i] = 0; }
}
__global__ void hist_kernel(const int* __restrict__ erow) {
    int e = blockIdx.x * blockDim.x + threadIdx.x;
    if (e < N_EDGES) atomicAdd(&g_cnt[erow[e]], 1);
}
__global__ void scan_kernel() {
    __shared__ int sdata[1024];
    __shared__ int s_carry;
    const int tid = threadIdx.x;
    if (tid == 0) s_carry = 0;
    __syncthreads();
    for (int base = 0; base < N_NODES; base += 1024) {
        int v = (base + tid < N_NODES) ? g_cnt[base + tid] : 0;
        sdata[tid] = v;
        __syncthreads();
        #pragma unroll
        for (int off = 1; off < 1024; off <<= 1) {
            int t = (tid >= off) ? sdata[tid - off] : 0;
            __syncthreads();
            sdata[tid] += t;
            __syncthreads();
        }
        int incl = sdata[tid];
        if (base + tid < N_NODES) g_rptr[base + tid + 1] = s_carry + incl;
        __syncthreads();
        if (tid == 1023) s_carry += incl;
        __syncthreads();
    }
    if (tid == 0) g_rptr[0] = 0;
}
__global__ void scatter_kernel(const int* __restrict__ erow) {
    int e = blockIdx.x * blockDim.x + threadIdx.x;
    if (e < N_EDGES) {
        int r = erow[e];
        int pos = g_rptr[r] + atomicAdd(&g_cur[r], 1);
        g_perm[pos] = e;
    }
}
__global__ void sortrows_kernel() {
    int r = blockIdx.x * blockDim.x + threadIdx.x;
    if (r >= N_NODES) return;
    int beg = g_rptr[r], end = g_rptr[r + 1];
    for (int i = beg + 1; i < end; i++) {
        int key = g_perm[i];
        int j = i - 1;
        while (j >= beg && g_perm[j] > key) { g_perm[j + 1] = g_perm[j]; j--; }
        g_perm[j + 1] = key;
    }
}

// ---------------- SpMM (+ReLU): warp per row, gather g_h0 -> g_h1 ----------
__global__ void __launch_bounds__(256) spmm_relu_kernel(
    const int* __restrict__ ecol, const float* __restrict__ eval)
{
    int gw   = (blockIdx.x * blockDim.x + threadIdx.x) >> 5;
    int lane = threadIdx.x & 31;
    if (gw >= N_NODES) return;
    int beg = g_rptr[gw], end = g_rptr[gw + 1];

    float4 acc0 = make_float4(0.f, 0.f, 0.f, 0.f);
    float4 acc1 = acc0, acc2 = acc0, acc3 = acc0;

    for (int b = beg; b < end; b += 32) {
        int n = end - b;
        if (n > 32) n = 32;
        int   c = 0;
        float w = 0.f;
        if (lane < n) {
            int id = g_perm[b + lane];
            c = ecol[id];
            w = eval[id];
        }
        for (int j = 0; j < n; j++) {
            int   cj = __shfl_sync(0xffffffffu, c, j);
            float wj = __shfl_sync(0xffffffffu, w, j);
            const float4* hr = reinterpret_cast<const float4*>(g_h0 + (size_t)cj * D_HID);
            fma4(acc0, wj, hr[lane]);
            fma4(acc1, wj, hr[lane + 32]);
            fma4(acc2, wj, hr[lane + 64]);
            fma4(acc3, wj, hr[lane + 96]);
        }
    }
    float4* o = reinterpret_cast<float4*>(g_h1 + (size_t)gw * D_HID);
    o[lane]      = relu4(acc0);
    o[lane + 32] = relu4(acc1);
    o[lane + 64] = relu4(acc2);
    o[lane + 96] = relu4(acc3);
}

// ---------------- mma.sync bf16-split GEMM ----------------
// C[M,N] = A[M,512] * W[N,512]^T.
// CTA tile 128x128, 8 warps (2m x 4n), warp tile 64x32.
// K chunks of 64, double-buffered SMEM. bf16 split: hi*hi + hi*lo + lo*hi.
// SMEM per stage: AHI(16K) ALO(16K) BHI(16K) BLO(16K); 2 stages = 128KB.
// Row layout: 128 bytes/row (64 bf16), 16B chunk c swizzled: c ^= (row & 7).
#define MG_STAGE  65536
#define MG_A_HI   0
#define MG_A_LO   16384
#define MG_B_HI   32768
#define MG_B_LO   49152
#define MG_TOTAL  (2 * MG_STAGE)

template <bool RELU>
__global__ void __launch_bounds__(256) gemm_mma_kernel(
    const float* __restrict__ A,
    const __nv_bfloat16* __restrict__ Bhi,
    const __nv_bfloat16* __restrict__ Blo,
    float* __restrict__ C, int M, int N)
{
    extern __shared__ char smem[];
    const int tid  = threadIdx.x;
    const int wid  = tid >> 5;
    const int lane = tid & 31;
    const int bm = blockIdx.y * 128;
    const int bn = blockIdx.x * 128;
    const int wm = wid >> 2;       // 0..1
    const int wn = wid & 3;        // 0..3
    const uint32_t sb = smem_u32(smem);

    float d[4][4][4];
    #pragma unroll
    for (int mi = 0; mi < 4; mi++)
        #pragma unroll
        for (int ni = 0; ni < 4; ni++)
            #pragma unroll
            for (int q = 0; q < 4; q++) d[mi][ni][q] = 0.f;

    // prefetch registers
    float4 pa[8];
    uint4  pbh[4], pbl[4];

    // ldmatrix lane decomposition
    const int lmat   = lane >> 3;
    const int a_rit  = ((lmat & 1) << 3) + (lane & 7);   // A: mat0/2 rows 0-7, mat1/3 rows 8-15
    const int a_cadd = lmat >> 1;                        // A: mats 0,1 chunk+0; 2,3 chunk+1
    const int b_rit  = ((lmat >> 1) << 3) + (lane & 7);  // B: mats 0,1 n rows 0-7; 2,3 rows 8-15
    const int b_cadd = lmat & 1;                         // B: mats 0,2 chunk+0; 1,3 chunk+1

    int arow[4], brow[2];
    #pragma unroll
    for (int mi = 0; mi < 4; mi++) arow[mi] = wm * 64 + mi * 16 + a_rit;
    #pragma unroll
    for (int np = 0; np < 2; np++) brow[np] = wn * 32 + np * 16 + b_rit;

    #define LDG_CHUNK(kc) do {                                                     \
        const int k0_ = (kc) * 64;                                                 \
        _Pragma("unroll")                                                          \
        for (int i = 0; i < 8; i++) {                                              \
            int idx = tid + i * 256;                                               \
            int r = idx >> 4, c4 = idx & 15;                                       \
            int gr = bm + r;                                                       \
            pa[i] = (gr < M)                                                       \
                ? __ldg(reinterpret_cast<const float4*>(A + (size_t)gr * 512 + k0_ + c4 * 4)) \
                : make_float4(0.f, 0.f, 0.f, 0.f);                                 \
        }                                                                          \
        _Pragma("unroll")                                                          \
        for (int i = 0; i < 4; i++) {                                              \
            int idx = tid + i * 256;                                               \
            int r = idx >> 3, c = idx & 7;                                         \
            size_t go = (size_t)(bn + r) * 512 + k0_;                              \
            pbh[i] = __ldg(reinterpret_cast<const uint4*>(Bhi + go) + c);          \
            pbl[i] = __ldg(reinterpret_cast<const uint4*>(Blo + go) + c);          \
        }                                                                          \
    } while (0)

    #define STS_CHUNK(s) do {                                                      \
        char* st_ = smem + (s) * MG_STAGE;                                         \
        _Pragma("unroll")                                                          \
        for (int i = 0; i < 8; i++) {                                              \
            int idx = tid + i * 256;                                               \
            int r = idx >> 4, c4 = idx & 15;                                       \
            float4 v = pa[i];                                                      \
            uint32_t hi01 = pack_bf16x2(v.y, v.x);                                 \
            uint32_t hi23 = pack_bf16x2(v.w, v.z);                                 \
            float h0f = __uint_as_float(hi01 << 16);                               \
            float h1f = __uint_as_float(hi01 & 0xFFFF0000u);                       \
            float h2f = __uint_as_float(hi23 << 16);                               \
            float h3f = __uint_as_float(hi23 & 0xFFFF0000u);                       \
            uint32_t lo01 = pack_bf16x2(v.y - h1f, v.x - h0f);                     \
            uint32_t lo23 = pack_bf16x2(v.w - h3f, v.z - h2f);                     \
            int c = c4 >> 1, half = (c4 & 1) * 8;                                  \
            uint32_t off = (uint32_t)(r * 128 + ((c ^ (r & 7)) << 4) + half);      \
            *reinterpret_cast<uint2*>(st_ + MG_A_HI + off) = make_uint2(hi01, hi23); \
            *reinterpret_cast<uint2*>(st_ + MG_A_LO + off) = make_uint2(lo01, lo23); \
        }                                                                          \
        _Pragma("unroll")                                                          \
        for (int i = 0; i < 4; i++) {                                              \
            int idx = tid + i * 256;                                               \
            int r = idx >> 3, c = idx & 7;                                         \
            uint32_t off = (uint32_t)(r * 128 + ((c ^ (r & 7)) << 4));             \
            *reinterpret_cast<uint4*>(st_ + MG_B_HI + off) = pbh[i];               \
            *reinterpret_cast<uint4*>(st_ + MG_B_LO + off) = pbl[i];               \
        }                                                                          \
    } while (0)

    LDG_CHUNK(0);
    STS_CHUNK(0);
    __syncthreads();

    for (int kc = 0; kc < 8; kc++) {
        if (kc < 7) LDG_CHUNK(kc + 1);

        // compute on stage kc&1
        {
            const uint32_t bah = sb + (kc & 1) * MG_STAGE + MG_A_HI;
            const uint32_t bal = sb + (kc & 1) * MG_STAGE + MG_A_LO;
            const uint32_t bbh = sb + (kc & 1) * MG_STAGE + MG_B_HI;
            const uint32_t bbl = sb + (kc & 1) * MG_STAGE + MG_B_LO;
            #pragma unroll
            for (int ks = 0; ks < 4; ks++) {
                uint32_t ahi[4][4], alo[4][4], bhif[2][4], blof[2][4];
                #pragma unroll
                for (int mi = 0; mi < 4; mi++) {
                    int cA = ks * 2 + a_cadd;
                    uint32_t off = (uint32_t)(arow[mi] * 128 + ((cA ^ (arow[mi] & 7)) << 4));
                    ldsm4(ahi[mi], bah + off);
                    ldsm4(alo[mi], bal + off);
                }
                #pragma unroll
                for (int np = 0; np < 2; np++) {
                    int cB = ks * 2 + b_cadd;
                    uint32_t off = (uint32_t)(brow[np] * 128 + ((cB ^ (brow[np] & 7)) << 4));
                    ldsm4(bhif[np], bbh + off);
                    ldsm4(blof[np], bbl + off);
                }
                #pragma unroll
                for (int mi = 0; mi < 4; mi++) {
                    #pragma unroll
                    for (int np = 0; np < 2; np++) {
                        #pragma unroll
                        for (int sub = 0; sub < 2; sub++) {
                            const int ni = np * 2 + sub;
                            uint32_t b0h = bhif[np][sub * 2], b1h = bhif[np][sub * 2 + 1];
                            uint32_t b0l = blof[np][sub * 2], b1l = blof[np][sub * 2 + 1];
                            mma16816(d[mi][ni], ahi[mi], b0h, b1h);
                            mma16816(d[mi][ni], ahi[mi], b0l, b1l);
                            mma16816(d[mi][ni], alo[mi], b0h, b1h);
                        }
                    }
                }
            }
        }

        if (kc < 7) STS_CHUNK((kc + 1) & 1);
        __syncthreads();
    }

    // epilogue: D frag (16x8): c0,c1 row=grp col=tg*2; c2,c3 row=grp+8
    const int grp = lane >> 2;
    const int tg  = lane & 3;
    #pragma unroll
    for (int mi = 0; mi < 4; mi++) {
        #pragma unroll
        for (int ni = 0; ni < 4; ni++) {
            int row = bm + wm * 64 + mi * 16 + grp;
            int col = bn + wn * 32 + ni * 8 + tg * 2;
            float2 v0 = make_float2(d[mi][ni][0], d[mi][ni][1]);
            float2 v1 = make_float2(d[mi][ni][2], d[mi][ni][3]);
            if (RELU) {
                v0.x = fmaxf(v0.x, 0.f); v0.y = fmaxf(v0.y, 0.f);
                v1.x = fmaxf(v1.x, 0.f); v1.y = fmaxf(v1.y, 0.f);
            }
            if (row < M)
                *reinterpret_cast<float2*>(C + (size_t)row * N + col) = v0;
            if (row + 8 < M)
                *reinterpret_cast<float2*>(C + (size_t)(row + 8) * N + col) = v1;
        }
    }
    #undef LDG_CHUNK
    #undef STS_CHUNK
}

// ---------------- launch ----------------
extern "C" void kernel_launch(void* const* d_in, const int* in_sizes, int n_in,
                              void* d_out, int out_size)
{
    const float* x    = (const float*)d_in[0];
    const int*   erow = (const int*)  d_in[1];
    const int*   ecol = (const int*)  d_in[2];
    const float* eval = (const float*)d_in[3];
    const float* W0   = (const float*)d_in[4];
    const float* W1   = (const float*)d_in[5];
    const float* W2   = (const float*)d_in[6];
    float* out = (float*)d_out;

    float *h0, *h1;
    cudaGetSymbolAddress((void**)&h0, g_h0);
    cudaGetSymbolAddress((void**)&h1, g_h1);
    __nv_bfloat16 *whi, *wlo;
    cudaGetSymbolAddress((void**)&whi, g_Whi);
    cudaGetSymbolAddress((void**)&wlo, g_Wlo);

    cudaFuncSetAttribute(gemm_mma_kernel<false>,
                         cudaFuncAttributeMaxDynamicSharedMemorySize, MG_TOTAL);
    cudaFuncSetAttribute(gemm_mma_kernel<true>,
                         cudaFuncAttributeMaxDynamicSharedMemorySize, MG_TOTAL);

    // weight split conversion + CSR build (independent of GEMM0)
    convert_w_kernel<<<(W_TOTAL + 255) / 256, 256>>>(W0, W1, W2);
    zero_counts_kernel<<<(N_NODES + 255) / 256, 256>>>();
    hist_kernel<<<(N_EDGES + 255) / 256, 256>>>(erow);
    scan_kernel<<<1, 1024>>>();
    scatter_kernel<<<(N_EDGES + 255) / 256, 256>>>(erow);
    sortrows_kernel<<<(N_NODES + 127) / 128, 128>>>();

    const int mtiles = (N_NODES + 127) / 128;
    // h0 = x @ W0^T
    gemm_mma_kernel<false><<<dim3(4, mtiles), 256, MG_TOTAL>>>(
        x, whi, wlo, h0, N_NODES, D_HID);
    // h1 = relu(A @ h0)
    spmm_relu_kernel<<<(N_NODES * 32 + 255) / 256, 256>>>(ecol, eval);
    // h0 = relu(h1 @ W1^T)
    gemm_mma_kernel<true><<<dim3(4, mtiles), 256, MG_TOTAL>>>(
        h1, whi + 262144, wlo + 262144, h0, N_NODES, D_HID);
    // out = h0 @ W2^T
    gemm_mma_kernel<false><<<dim3(2, mtiles), 256, MG_TOTAL>>>(
        h0, whi + 524288, wlo + 524288, out, N_NODES, D_OUT);
}

// round 7
// speedup vs baseline: 2.3086x; 1.2095x over previous
#include <cuda_runtime.h>
#include <cuda_bf16.h>
#include <cstdint>
#include <cstddef>

#define N_NODES 100000
#define N_EDGES 3200000
#define D_IN    512
#define D_HID   512
#define D_OUT   256

// ---------------- scratch (no cudaMalloc allowed) ----------------
__device__ float g_h0[(size_t)N_NODES * D_HID];   // 204.8 MB
__device__ float g_h1[(size_t)N_NODES * D_HID];   // 204.8 MB
__device__ int   g_rptr[N_NODES + 1];
__device__ int   g_cnt[N_NODES];
__device__ int   g_cur[N_NODES];
__device__ int   g_perm[N_EDGES];
#define SCAN_BLOCKS ((N_NODES + 1023) / 1024)     // 98
__device__ int   g_bsum[SCAN_BLOCKS];
// pre-converted weights (bf16 hi/lo split): W0 @0, W1 @262144, W2 @524288
#define W_TOTAL 655360
__device__ __nv_bfloat16 g_Whi[W_TOTAL];
__device__ __nv_bfloat16 g_Wlo[W_TOTAL];

// ---------------- helpers ----------------
__device__ __forceinline__ void fma4(float4& a, float w, const float4 v) {
    a.x = fmaf(w, v.x, a.x); a.y = fmaf(w, v.y, a.y);
    a.z = fmaf(w, v.z, a.z); a.w = fmaf(w, v.w, a.w);
}
__device__ __forceinline__ float4 relu4(float4 a) {
    a.x = fmaxf(a.x, 0.f); a.y = fmaxf(a.y, 0.f);
    a.z = fmaxf(a.z, 0.f); a.w = fmaxf(a.w, 0.f);
    return a;
}
__device__ __forceinline__ uint32_t smem_u32(const void* p) {
    uint32_t a;
    asm("{ .reg .u64 t; cvta.to.shared.u64 t, %1; cvt.u32.u64 %0, t; }" : "=r"(a) : "l"(p));
    return a;
}
__device__ __forceinline__ uint32_t pack_bf16x2(float hi_elem, float lo_elem) {
    uint32_t r;
    asm("cvt.rn.bf16x2.f32 %0, %1, %2;" : "=r"(r) : "f"(hi_elem), "f"(lo_elem));
    return r;
}
__device__ __forceinline__ void ldsm4(uint32_t* r, uint32_t addr) {
    asm volatile("ldmatrix.sync.aligned.m8n8.x4.shared.b16 {%0,%1,%2,%3}, [%4];"
                 : "=r"(r[0]), "=r"(r[1]), "=r"(r[2]), "=r"(r[3]) : "r"(addr));
}
__device__ __forceinline__ void mma16816(float* d, const uint32_t* a,
                                         uint32_t b0, uint32_t b1) {
    asm volatile(
        "mma.sync.aligned.m16n8k16.row.col.f32.bf16.bf16.f32 "
        "{%0,%1,%2,%3}, {%4,%5,%6,%7}, {%8,%9}, {%0,%1,%2,%3};"
        : "+f"(d[0]), "+f"(d[1]), "+f"(d[2]), "+f"(d[3])
        : "r"(a[0]), "r"(a[1]), "r"(a[2]), "r"(a[3]), "r"(b0), "r"(b1));
}

// ---------------- weight conversion (tiny) ----------------
__global__ void convert_w_kernel(const float* __restrict__ W0,
                                 const float* __restrict__ W1,
                                 const float* __restrict__ W2) {
    int i = blockIdx.x * blockDim.x + threadIdx.x;
    if (i >= W_TOTAL) return;
    float v = (i < 262144) ? W0[i] : (i < 524288) ? W1[i - 262144] : W2[i - 524288];
    __nv_bfloat16 h = __float2bfloat16(v);
    g_Whi[i] = h;
    g_Wlo[i] = __float2bfloat16(v - __bfloat162float(h));
}

// ---------------- CSR build ----------------
__global__ void zero_counts_kernel() {
    int i = blockIdx.x * blockDim.x + threadIdx.x;
    if (i < N_NODES) { g_cnt[i] = 0; g_cur[i] = 0; }
}
__global__ void hist_kernel(const int* __restrict__ erow) {
    int e = blockIdx.x * blockDim.x + threadIdx.x;
    if (e < N_EDGES) atomicAdd(&g_cnt[erow[e]], 1);
}
// 3-pass parallel scan: block scans -> block-sum scan -> offset add
__global__ void scan1_kernel() {
    __shared__ int s[1024];
    const int b = blockIdx.x, t = threadIdx.x;
    const int i = b * 1024 + t;
    int v = (i < N_NODES) ? g_cnt[i] : 0;
    s[t] = v;
    __syncthreads();
    #pragma unroll
    for (int off = 1; off < 1024; off <<= 1) {
        int x = (t >= off) ? s[t - off] : 0;
        __syncthreads();
        s[t] += x;
        __syncthreads();
    }
    if (i < N_NODES) g_rptr[i + 1] = s[t];
    if (t == 1023) g_bsum[b] = s[1023];
}
__global__ void scan2_kernel() {
    __shared__ int s[128];
    const int t = threadIdx.x;
    int v = (t < SCAN_BLOCKS) ? g_bsum[t] : 0;
    s[t] = v;
    __syncthreads();
    #pragma unroll
    for (int off = 1; off < 128; off <<= 1) {
        int x = (t >= off) ? s[t - off] : 0;
        __syncthreads();
        s[t] += x;
        __syncthreads();
    }
    if (t < SCAN_BLOCKS) g_bsum[t] = s[t] - v;   // exclusive
}
__global__ void scan3_kernel() {
    const int b = blockIdx.x, t = threadIdx.x;
    const int i = b * 1024 + t;
    if (i < N_NODES) g_rptr[i + 1] += g_bsum[b];
    if (i == 0) g_rptr[0] = 0;
}
__global__ void scatter_kernel(const int* __restrict__ erow) {
    int e = blockIdx.x * blockDim.x + threadIdx.x;
    if (e < N_EDGES) {
        int r = erow[e];
        int pos = g_rptr[r] + atomicAdd(&g_cur[r], 1);
        g_perm[pos] = e;
    }
}

// ---------------- SpMM (+ReLU), feature-chunked for L2 residency ----------
// chunk = 128 floats (512B) of the 512-wide feature dim; per-pass gather
// working set = 100k * 512B = 51.2 MB << L2. Edge lists / output streamed
// with evict-first hints so the hot gather set stays resident.
__global__ void __launch_bounds__(256) spmm_relu_chunk_kernel(
    const int* __restrict__ ecol, const float* __restrict__ eval, int chunk)
{
    int gw   = (blockIdx.x * blockDim.x + threadIdx.x) >> 5;
    int lane = threadIdx.x & 31;
    if (gw >= N_NODES) return;
    int beg = g_rptr[gw], end = g_rptr[gw + 1];
    const float* hbase = g_h0 + (size_t)chunk * 128 + lane * 4;

    float4 acc = make_float4(0.f, 0.f, 0.f, 0.f);

    for (int b = beg; b < end; b += 32) {
        int n = end - b;
        if (n > 32) n = 32;
        int   c = 0;
        float w = 0.f;
        if (lane < n) {
            int id = __ldcs(g_perm + b + lane);
            c = __ldcs(ecol + id);
            w = __ldcs(eval + id);
        }
        for (int j = 0; j < n; j++) {
            int   cj = __shfl_sync(0xffffffffu, c, j);
            float wj = __shfl_sync(0xffffffffu, w, j);
            float4 v = *reinterpret_cast<const float4*>(hbase + (size_t)cj * 512);
            fma4(acc, wj, v);
        }
    }
    float* o = g_h1 + (size_t)gw * 512 + chunk * 128 + lane * 4;
    __stcs(reinterpret_cast<float4*>(o), relu4(acc));
}

// ---------------- mma.sync bf16-split GEMM ----------------
// C[M,N] = A[M,512] * W[N,512]^T.
// CTA tile 128x128, 8 warps (2m x 4n), warp tile 64x32.
// K chunks of 64, double-buffered SMEM. bf16 split: hi*hi + hi*lo + lo*hi.
#define MG_STAGE  65536
#define MG_A_HI   0
#define MG_A_LO   16384
#define MG_B_HI   32768
#define MG_B_LO   49152
#define MG_TOTAL  (2 * MG_STAGE)

template <bool RELU>
__global__ void __launch_bounds__(256) gemm_mma_kernel(
    const float* __restrict__ A,
    const __nv_bfloat16* __restrict__ Bhi,
    const __nv_bfloat16* __restrict__ Blo,
    float* __restrict__ C, int M, int N)
{
    extern __shared__ char smem[];
    const int tid  = threadIdx.x;
    const int wid  = tid >> 5;
    const int lane = tid & 31;
    const int bm = blockIdx.y * 128;
    const int bn = blockIdx.x * 128;
    const int wm = wid >> 2;       // 0..1
    const int wn = wid & 3;        // 0..3
    const uint32_t sb = smem_u32(smem);

    float d[4][4][4];
    #pragma unroll
    for (int mi = 0; mi < 4; mi++)
        #pragma unroll
        for (int ni = 0; ni < 4; ni++)
            #pragma unroll
            for (int q = 0; q < 4; q++) d[mi][ni][q] = 0.f;

    float4 pa[8];
    uint4  pbh[4], pbl[4];

    const int lmat   = lane >> 3;
    const int a_rit  = ((lmat & 1) << 3) + (lane & 7);
    const int a_cadd = lmat >> 1;
    const int b_rit  = ((lmat >> 1) << 3) + (lane & 7);
    const int b_cadd = lmat & 1;

    int arow[4], brow[2];
    #pragma unroll
    for (int mi = 0; mi < 4; mi++) arow[mi] = wm * 64 + mi * 16 + a_rit;
    #pragma unroll
    for (int np = 0; np < 2; np++) brow[np] = wn * 32 + np * 16 + b_rit;

    #define LDG_CHUNK(kc) do {                                                     \
        const int k0_ = (kc) * 64;                                                 \
        _Pragma("unroll")                                                          \
        for (int i = 0; i < 8; i++) {                                              \
            int idx = tid + i * 256;                                               \
            int r = idx >> 4, c4 = idx & 15;                                       \
            int gr = bm + r;                                                       \
            pa[i] = (gr < M)                                                       \
                ? __ldg(reinterpret_cast<const float4*>(A + (size_t)gr * 512 + k0_ + c4 * 4)) \
                : make_float4(0.f, 0.f, 0.f, 0.f);                                 \
        }                                                                          \
        _Pragma("unroll")                                                          \
        for (int i = 0; i < 4; i++) {                                              \
            int idx = tid + i * 256;                                               \
            int r = idx >> 3, c = idx & 7;                                         \
            size_t go = (size_t)(bn + r) * 512 + k0_;                              \
            pbh[i] = __ldg(reinterpret_cast<const uint4*>(Bhi + go) + c);          \
            pbl[i] = __ldg(reinterpret_cast<const uint4*>(Blo + go) + c);          \
        }                                                                          \
    } while (0)

    #define STS_CHUNK(s) do {                                                      \
        char* st_ = smem + (s) * MG_STAGE;                                         \
        _Pragma("unroll")                                                          \
        for (int i = 0; i < 8; i++) {                                              \
            int idx = tid + i * 256;                                               \
            int r = idx >> 4, c4 = idx & 15;                                       \
            float4 v = pa[i];                                                      \
            uint32_t hi01 = pack_bf16x2(v.y, v.x);                                 \
            uint32_t hi23 = pack_bf16x2(v.w, v.z);                                 \
            float h0f = __uint_as_float(hi01 << 16);                               \
            float h1f = __uint_as_float(hi01 & 0xFFFF0000u);                       \
            float h2f = __uint_as_float(hi23 << 16);                               \
            float h3f = __uint_as_float(hi23 & 0xFFFF0000u);                       \
            uint32_t lo01 = pack_bf16x2(v.y - h1f, v.x - h0f);                     \
            uint32_t lo23 = pack_bf16x2(v.w - h3f, v.z - h2f);                     \
            int c = c4 >> 1, half = (c4 & 1) * 8;                                  \
            uint32_t off = (uint32_t)(r * 128 + ((c ^ (r & 7)) << 4) + half);      \
            *reinterpret_cast<uint2*>(st_ + MG_A_HI + off) = make_uint2(hi01, hi23); \
            *reinterpret_cast<uint2*>(st_ + MG_A_LO + off) = make_uint2(lo01, lo23); \
        }                                                                          \
        _Pragma("unroll")                                                          \
        for (int i = 0; i < 4; i++) {                                              \
            int idx = tid + i * 256;                                               \
            int r = idx >> 3, c = idx & 7;                                         \
            uint32_t off = (uint32_t)(r * 128 + ((c ^ (r & 7)) << 4));             \
            *reinterpret_cast<uint4*>(st_ + MG_B_HI + off) = pbh[i];               \
            *reinterpret_cast<uint4*>(st_ + MG_B_LO + off) = pbl[i];               \
        }                                                                          \
    } while (0)

    LDG_CHUNK(0);
    STS_CHUNK(0);
    __syncthreads();

    for (int kc = 0; kc < 8; kc++) {
        if (kc < 7) LDG_CHUNK(kc + 1);

        {
            const uint32_t bah = sb + (kc & 1) * MG_STAGE + MG_A_HI;
            const uint32_t bal = sb + (kc & 1) * MG_STAGE + MG_A_LO;
            const uint32_t bbh = sb + (kc & 1) * MG_STAGE + MG_B_HI;
            const uint32_t bbl = sb + (kc & 1) * MG_STAGE + MG_B_LO;
            #pragma unroll
            for (int ks = 0; ks < 4; ks++) {
                uint32_t ahi[4][4], alo[4][4], bhif[2][4], blof[2][4];
                #pragma unroll
                for (int mi = 0; mi < 4; mi++) {
                    int cA = ks * 2 + a_cadd;
                    uint32_t off = (uint32_t)(arow[mi] * 128 + ((cA ^ (arow[mi] & 7)) << 4));
                    ldsm4(ahi[mi], bah + off);
                    ldsm4(alo[mi], bal + off);
                }
                #pragma unroll
                for (int np = 0; np < 2; np++) {
                    int cB = ks * 2 + b_cadd;
                    uint32_t off = (uint32_t)(brow[np] * 128 + ((cB ^ (brow[np] & 7)) << 4));
                    ldsm4(bhif[np], bbh + off);
                    ldsm4(blof[np], bbl + off);
                }
                #pragma unroll
                for (int mi = 0; mi < 4; mi++) {
                    #pragma unroll
                    for (int np = 0; np < 2; np++) {
                        #pragma unroll
                        for (int sub = 0; sub < 2; sub++) {
                            const int ni = np * 2 + sub;
                            uint32_t b0h = bhif[np][sub * 2], b1h = bhif[np][sub * 2 + 1];
                            uint32_t b0l = blof[np][sub * 2], b1l = blof[np][sub * 2 + 1];
                            mma16816(d[mi][ni], ahi[mi], b0h, b1h);
                            mma16816(d[mi][ni], ahi[mi], b0l, b1l);
                            mma16816(d[mi][ni], alo[mi], b0h, b1h);
                        }
                    }
                }
            }
        }

        if (kc < 7) STS_CHUNK((kc + 1) & 1);
        __syncthreads();
    }

    const int grp = lane >> 2;
    const int tg  = lane & 3;
    #pragma unroll
    for (int mi = 0; mi < 4; mi++) {
        #pragma unroll
        for (int ni = 0; ni < 4; ni++) {
            int row = bm + wm * 64 + mi * 16 + grp;
            int col = bn + wn * 32 + ni * 8 + tg * 2;
            float2 v0 = make_float2(d[mi][ni][0], d[mi][ni][1]);
            float2 v1 = make_float2(d[mi][ni][2], d[mi][ni][3]);
            if (RELU) {
                v0.x = fmaxf(v0.x, 0.f); v0.y = fmaxf(v0.y, 0.f);
                v1.x = fmaxf(v1.x, 0.f); v1.y = fmaxf(v1.y, 0.f);
            }
            if (row < M)
                *reinterpret_cast<float2*>(C + (size_t)row * N + col) = v0;
            if (row + 8 < M)
                *reinterpret_cast<float2*>(C + (size_t)(row + 8) * N + col) = v1;
        }
    }
    #undef LDG_CHUNK
    #undef STS_CHUNK
}

// ---------------- launch ----------------
extern "C" void kernel_launch(void* const* d_in, const int* in_sizes, int n_in,
                              void* d_out, int out_size)
{
    const float* x    = (const float*)d_in[0];
    const int*   erow = (const int*)  d_in[1];
    const int*   ecol = (const int*)  d_in[2];
    const float* eval = (const float*)d_in[3];
    const float* W0   = (const float*)d_in[4];
    const float* W1   = (const float*)d_in[5];
    const float* W2   = (const float*)d_in[6];
    float* out = (float*)d_out;

    float *h0, *h1;
    cudaGetSymbolAddress((void**)&h0, g_h0);
    cudaGetSymbolAddress((void**)&h1, g_h1);
    __nv_bfloat16 *whi, *wlo;
    cudaGetSymbolAddress((void**)&whi, g_Whi);
    cudaGetSymbolAddress((void**)&wlo, g_Wlo);

    cudaFuncSetAttribute(gemm_mma_kernel<false>,
                         cudaFuncAttributeMaxDynamicSharedMemorySize, MG_TOTAL);
    cudaFuncSetAttribute(gemm_mma_kernel<true>,
                         cudaFuncAttributeMaxDynamicSharedMemorySize, MG_TOTAL);

    // weight split conversion + CSR build (independent of GEMM0)
    convert_w_kernel<<<(W_TOTAL + 255) / 256, 256>>>(W0, W1, W2);
    zero_counts_kernel<<<(N_NODES + 255) / 256, 256>>>();
    hist_kernel<<<(N_EDGES + 255) / 256, 256>>>(erow);
    scan1_kernel<<<SCAN_BLOCKS, 1024>>>();
    scan2_kernel<<<1, 128>>>();
    scan3_kernel<<<SCAN_BLOCKS, 1024>>>();
    scatter_kernel<<<(N_EDGES + 255) / 256, 256>>>(erow);

    const int mtiles = (N_NODES + 127) / 128;
    // h0 = x @ W0^T
    gemm_mma_kernel<false><<<dim3(4, mtiles), 256, MG_TOTAL>>>(
        x, whi, wlo, h0, N_NODES, D_HID);
    // h1 = relu(A @ h0), 4 feature-chunk passes for L2 residency
    for (int chunk = 0; chunk < 4; chunk++)
        spmm_relu_chunk_kernel<<<(N_NODES * 32 + 255) / 256, 256>>>(ecol, eval, chunk);
    // h0 = relu(h1 @ W1^T)
    gemm_mma_kernel<true><<<dim3(4, mtiles), 256, MG_TOTAL>>>(
        h1, whi + 262144, wlo + 262144, h0, N_NODES, D_HID);
    // out = h0 @ W2^T
    gemm_mma_kernel<false><<<dim3(2, mtiles), 256, MG_TOTAL>>>(
        h0, whi + 524288, wlo + 524288, out, N_NODES, D_OUT);
}

// round 8
// speedup vs baseline: 2.6196x; 1.1347x over previous
#include <cuda_runtime.h>
#include <cuda_bf16.h>
#include <cstdint>
#include <cstddef>

#define N_NODES 100000
#define N_EDGES 3200000
#define D_IN    512
#define D_HID   512
#define D_OUT   256

// ---------------- scratch (no cudaMalloc allowed) ----------------
__device__ float g_h0[(size_t)N_NODES * D_HID];   // 204.8 MB
__device__ float g_h1[(size_t)N_NODES * D_HID];   // 204.8 MB
__device__ int   g_rptr[N_NODES + 1];
__device__ int   g_cnt[N_NODES];
__device__ int   g_cur[N_NODES];
__device__ int2  g_edge[N_EDGES];                 // row-sorted {col, w bits}
#define SCAN_BLOCKS ((N_NODES + 1023) / 1024)     // 98
__device__ int   g_bsum[SCAN_BLOCKS];
// pre-converted weights (bf16 hi/lo split): W0 @0, W1 @262144, W2 @524288
#define W_TOTAL 655360
__device__ __nv_bfloat16 g_Whi[W_TOTAL];
__device__ __nv_bfloat16 g_Wlo[W_TOTAL];

// ---------------- helpers ----------------
__device__ __forceinline__ void fma4(float4& a, float w, const float4 v) {
    a.x = fmaf(w, v.x, a.x); a.y = fmaf(w, v.y, a.y);
    a.z = fmaf(w, v.z, a.z); a.w = fmaf(w, v.w, a.w);
}
__device__ __forceinline__ float4 relu4(float4 a) {
    a.x = fmaxf(a.x, 0.f); a.y = fmaxf(a.y, 0.f);
    a.z = fmaxf(a.z, 0.f); a.w = fmaxf(a.w, 0.f);
    return a;
}
__device__ __forceinline__ uint32_t smem_u32(const void* p) {
    uint32_t a;
    asm("{ .reg .u64 t; cvta.to.shared.u64 t, %1; cvt.u32.u64 %0, t; }" : "=r"(a) : "l"(p));
    return a;
}
__device__ __forceinline__ uint32_t pack_bf16x2(float hi_elem, float lo_elem) {
    uint32_t r;
    asm("cvt.rn.bf16x2.f32 %0, %1, %2;" : "=r"(r) : "f"(hi_elem), "f"(lo_elem));
    return r;
}
__device__ __forceinline__ void ldsm4(uint32_t* r, uint32_t addr) {
    asm volatile("ldmatrix.sync.aligned.m8n8.x4.shared.b16 {%0,%1,%2,%3}, [%4];"
                 : "=r"(r[0]), "=r"(r[1]), "=r"(r[2]), "=r"(r[3]) : "r"(addr));
}
__device__ __forceinline__ void mma16816(float* d, const uint32_t* a,
                                         uint32_t b0, uint32_t b1) {
    asm volatile(
        "mma.sync.aligned.m16n8k16.row.col.f32.bf16.bf16.f32 "
        "{%0,%1,%2,%3}, {%4,%5,%6,%7}, {%8,%9}, {%0,%1,%2,%3};"
        : "+f"(d[0]), "+f"(d[1]), "+f"(d[2]), "+f"(d[3])
        : "r"(a[0]), "r"(a[1]), "r"(a[2]), "r"(a[3]), "r"(b0), "r"(b1));
}

// ---------------- weight conversion (tiny) ----------------
__global__ void convert_w_kernel(const float* __restrict__ W0,
                                 const float* __restrict__ W1,
                                 const float* __restrict__ W2) {
    int i = blockIdx.x * blockDim.x + threadIdx.x;
    if (i >= W_TOTAL) return;
    float v = (i < 262144) ? W0[i] : (i < 524288) ? W1[i - 262144] : W2[i - 524288];
    __nv_bfloat16 h = __float2bfloat16(v);
    g_Whi[i] = h;
    g_Wlo[i] = __float2bfloat16(v - __bfloat162float(h));
}

// ---------------- CSR build ----------------
__global__ void zero_counts_kernel() {
    int i = blockIdx.x * blockDim.x + threadIdx.x;
    if (i < N_NODES) { g_cnt[i] = 0; g_cur[i] = 0; }
}
__global__ void hist_kernel(const int* __restrict__ erow) {
    int e = blockIdx.x * blockDim.x + threadIdx.x;
    if (e < N_EDGES) atomicAdd(&g_cnt[erow[e]], 1);
}
__global__ void scan1_kernel() {
    __shared__ int s[1024];
    const int b = blockIdx.x, t = threadIdx.x;
    const int i = b * 1024 + t;
    int v = (i < N_NODES) ? g_cnt[i] : 0;
    s[t] = v;
    __syncthreads();
    #pragma unroll
    for (int off = 1; off < 1024; off <<= 1) {
        int x = (t >= off) ? s[t - off] : 0;
        __syncthreads();
        s[t] += x;
        __syncthreads();
    }
    if (i < N_NODES) g_rptr[i + 1] = s[t];
    if (t == 1023) g_bsum[b] = s[1023];
}
__global__ void scan2_kernel() {
    __shared__ int s[128];
    const int t = threadIdx.x;
    int v = (t < SCAN_BLOCKS) ? g_bsum[t] : 0;
    s[t] = v;
    __syncthreads();
    #pragma unroll
    for (int off = 1; off < 128; off <<= 1) {
        int x = (t >= off) ? s[t - off] : 0;
        __syncthreads();
        s[t] += x;
        __syncthreads();
    }
    if (t < SCAN_BLOCKS) g_bsum[t] = s[t] - v;   // exclusive
}
__global__ void scan3_kernel() {
    const int b = blockIdx.x, t = threadIdx.x;
    const int i = b * 1024 + t;
    if (i < N_NODES) g_rptr[i + 1] += g_bsum[b];
    if (i == 0) g_rptr[0] = 0;
}
// scatter edges into row-sorted packed array {col, w}
__global__ void scatter_kernel(const int* __restrict__ erow,
                               const int* __restrict__ ecol,
                               const float* __restrict__ eval) {
    int e = blockIdx.x * blockDim.x + threadIdx.x;
    if (e < N_EDGES) {
        int r = erow[e];
        int pos = g_rptr[r] + atomicAdd(&g_cur[r], 1);
        g_edge[pos] = make_int2(ecol[e], __float_as_int(eval[e]));
    }
}

// ---------------- SpMM (+ReLU), feature-chunked for L2 residency ----------
__global__ void __launch_bounds__(256) spmm_relu_chunk_kernel(int chunk)
{
    int gw   = (blockIdx.x * blockDim.x + threadIdx.x) >> 5;
    int lane = threadIdx.x & 31;
    if (gw >= N_NODES) return;
    int beg = g_rptr[gw], end = g_rptr[gw + 1];
    const float* hbase = g_h0 + (size_t)chunk * 128 + lane * 4;

    float4 acc = make_float4(0.f, 0.f, 0.f, 0.f);

    for (int b = beg; b < end; b += 32) {
        int n = end - b;
        if (n > 32) n = 32;
        int   c = 0;
        float w = 0.f;
        if (lane < n) {
            int2 ed = __ldcs(g_edge + b + lane);
            c = ed.x;
            w = __int_as_float(ed.y);
        }
        for (int j = 0; j < n; j++) {
            int   cj = __shfl_sync(0xffffffffu, c, j);
            float wj = __shfl_sync(0xffffffffu, w, j);
            float4 v = *reinterpret_cast<const float4*>(hbase + (size_t)cj * 512);
            fma4(acc, wj, v);
        }
    }
    float* o = g_h1 + (size_t)gw * 512 + chunk * 128 + lane * 4;
    __stcs(reinterpret_cast<float4*>(o), relu4(acc));
}

// ---------------- mma.sync bf16-split GEMM ----------------
// C[M,N] = A[M,512] * W[N,512]^T.
// CTA tile 128x128, 16 warps (4m x 4n), warp tile 32x32.
// K chunks of 64, double-buffered SMEM. bf16 split: hi*hi + hi*lo + lo*hi.
#define MG_STAGE  65536
#define MG_A_HI   0
#define MG_A_LO   16384
#define MG_B_HI   32768
#define MG_B_LO   49152
#define MG_TOTAL  (2 * MG_STAGE)

template <bool RELU>
__global__ void __launch_bounds__(512) gemm_mma_kernel(
    const float* __restrict__ A,
    const __nv_bfloat16* __restrict__ Bhi,
    const __nv_bfloat16* __restrict__ Blo,
    float* __restrict__ C, int M, int N)
{
    extern __shared__ char smem[];
    const int tid  = threadIdx.x;
    const int wid  = tid >> 5;
    const int lane = tid & 31;
    const int bm = blockIdx.y * 128;
    const int bn = blockIdx.x * 128;
    const int wm = wid >> 2;       // 0..3
    const int wn = wid & 3;        // 0..3
    const uint32_t sb = smem_u32(smem);

    float d[2][4][4];
    #pragma unroll
    for (int mi = 0; mi < 2; mi++)
        #pragma unroll
        for (int ni = 0; ni < 4; ni++)
            #pragma unroll
            for (int q = 0; q < 4; q++) d[mi][ni][q] = 0.f;

    float4 pa[4];
    uint4  pbh[2], pbl[2];

    const int lmat   = lane >> 3;
    const int a_rit  = ((lmat & 1) << 3) + (lane & 7);
    const int a_cadd = lmat >> 1;
    const int b_rit  = ((lmat >> 1) << 3) + (lane & 7);
    const int b_cadd = lmat & 1;

    int arow[2], brow[2];
    #pragma unroll
    for (int mi = 0; mi < 2; mi++) arow[mi] = wm * 32 + mi * 16 + a_rit;
    #pragma unroll
    for (int np = 0; np < 2; np++) brow[np] = wn * 32 + np * 16 + b_rit;

    #define LDG_CHUNK(kc) do {                                                     \
        const int k0_ = (kc) * 64;                                                 \
        _Pragma("unroll")                                                          \
        for (int i = 0; i < 4; i++) {                                              \
            int idx = tid + i * 512;                                               \
            int r = idx >> 4, c4 = idx & 15;                                       \
            int gr = bm + r;                                                       \
            pa[i] = (gr < M)                                                       \
                ? __ldg(reinterpret_cast<const float4*>(A + (size_t)gr * 512 + k0_ + c4 * 4)) \
                : make_float4(0.f, 0.f, 0.f, 0.f);                                 \
        }                                                                          \
        _Pragma("unroll")                                                          \
        for (int i = 0; i < 2; i++) {                                              \
            int idx = tid + i * 512;                                               \
            int r = idx >> 3, c = idx & 7;                                         \
            size_t go = (size_t)(bn + r) * 512 + k0_;                              \
            pbh[i] = __ldg(reinterpret_cast<const uint4*>(Bhi + go) + c);          \
            pbl[i] = __ldg(reinterpret_cast<const uint4*>(Blo + go) + c);          \
        }                                                                          \
    } while (0)

    #define STS_CHUNK(s) do {                                                      \
        char* st_ = smem + (s) * MG_STAGE;                                         \
        _Pragma("unroll")                                                          \
        for (int i = 0; i < 4; i++) {                                              \
            int idx = tid + i * 512;                                               \
            int r = idx >> 4, c4 = idx & 15;                                       \
            float4 v = pa[i];                                                      \
            uint32_t hi01 = pack_bf16x2(v.y, v.x);                                 \
            uint32_t hi23 = pack_bf16x2(v.w, v.z);                                 \
            float h0f = __uint_as_float(hi01 << 16);                               \
            float h1f = __uint_as_float(hi01 & 0xFFFF0000u);                       \
            float h2f = __uint_as_float(hi23 << 16);                               \
            float h3f = __uint_as_float(hi23 & 0xFFFF0000u);                       \
            uint32_t lo01 = pack_bf16x2(v.y - h1f, v.x - h0f);                     \
            uint32_t lo23 = pack_bf16x2(v.w - h3f, v.z - h2f);                     \
            int c = c4 >> 1, half = (c4 & 1) * 8;                                  \
            uint32_t off = (uint32_t)(r * 128 + ((c ^ (r & 7)) << 4) + half);      \
            *reinterpret_cast<uint2*>(st_ + MG_A_HI + off) = make_uint2(hi01, hi23); \
            *reinterpret_cast<uint2*>(st_ + MG_A_LO + off) = make_uint2(lo01, lo23); \
        }                                                                          \
        _Pragma("unroll")                                                          \
        for (int i = 0; i < 2; i++) {                                              \
            int idx = tid + i * 512;                                               \
            int r = idx >> 3, c = idx & 7;                                         \
            uint32_t off = (uint32_t)(r * 128 + ((c ^ (r & 7)) << 4));             \
            *reinterpret_cast<uint4*>(st_ + MG_B_HI + off) = pbh[i];               \
            *reinterpret_cast<uint4*>(st_ + MG_B_LO + off) = pbl[i];               \
        }                                                                          \
    } while (0)

    LDG_CHUNK(0);
    STS_CHUNK(0);
    __syncthreads();

    for (int kc = 0; kc < 8; kc++) {
        if (kc < 7) LDG_CHUNK(kc + 1);

        {
            const uint32_t bah = sb + (kc & 1) * MG_STAGE + MG_A_HI;
            const uint32_t bal = sb + (kc & 1) * MG_STAGE + MG_A_LO;
            const uint32_t bbh = sb + (kc & 1) * MG_STAGE + MG_B_HI;
            const uint32_t bbl = sb + (kc & 1) * MG_STAGE + MG_B_LO;
            #pragma unroll
            for (int ks = 0; ks < 4; ks++) {
                uint32_t ahi[2][4], alo[2][4], bhif[2][4], blof[2][4];
                #pragma unroll
                for (int mi = 0; mi < 2; mi++) {
                    int cA = ks * 2 + a_cadd;
                    uint32_t off = (uint32_t)(arow[mi] * 128 + ((cA ^ (arow[mi] & 7)) << 4));
                    ldsm4(ahi[mi], bah + off);
                    ldsm4(alo[mi], bal + off);
                }
                #pragma unroll
                for (int np = 0; np < 2; np++) {
                    int cB = ks * 2 + b_cadd;
                    uint32_t off = (uint32_t)(brow[np] * 128 + ((cB ^ (brow[np] & 7)) << 4));
                    ldsm4(bhif[np], bbh + off);
                    ldsm4(blof[np], bbl + off);
                }
                #pragma unroll
                for (int mi = 0; mi < 2; mi++) {
                    #pragma unroll
                    for (int np = 0; np < 2; np++) {
                        #pragma unroll
                        for (int sub = 0; sub < 2; sub++) {
                            const int ni = np * 2 + sub;
                            uint32_t b0h = bhif[np][sub * 2], b1h = bhif[np][sub * 2 + 1];
                            uint32_t b0l = blof[np][sub * 2], b1l = blof[np][sub * 2 + 1];
                            mma16816(d[mi][ni], ahi[mi], b0h, b1h);
                            mma16816(d[mi][ni], ahi[mi], b0l, b1l);
                            mma16816(d[mi][ni], alo[mi], b0h, b1h);
                        }
                    }
                }
            }
        }

        if (kc < 7) STS_CHUNK((kc + 1) & 1);
        __syncthreads();
    }

    const int grp = lane >> 2;
    const int tg  = lane & 3;
    #pragma unroll
    for (int mi = 0; mi < 2; mi++) {
        #pragma unroll
        for (int ni = 0; ni < 4; ni++) {
            int row = bm + wm * 32 + mi * 16 + grp;
            int col = bn + wn * 32 + ni * 8 + tg * 2;
            float2 v0 = make_float2(d[mi][ni][0], d[mi][ni][1]);
            float2 v1 = make_float2(d[mi][ni][2], d[mi][ni][3]);
            if (RELU) {
                v0.x = fmaxf(v0.x, 0.f); v0.y = fmaxf(v0.y, 0.f);
                v1.x = fmaxf(v1.x, 0.f); v1.y = fmaxf(v1.y, 0.f);
            }
            if (row < M)
                *reinterpret_cast<float2*>(C + (size_t)row * N + col) = v0;
            if (row + 8 < M)
                *reinterpret_cast<float2*>(C + (size_t)(row + 8) * N + col) = v1;
        }
    }
    #undef LDG_CHUNK
    #undef STS_CHUNK
}

// ---------------- launch ----------------
extern "C" void kernel_launch(void* const* d_in, const int* in_sizes, int n_in,
                              void* d_out, int out_size)
{
    const float* x    = (const float*)d_in[0];
    const int*   erow = (const int*)  d_in[1];
    const int*   ecol = (const int*)  d_in[2];
    const float* eval = (const float*)d_in[3];
    const float* W0   = (const float*)d_in[4];
    const float* W1   = (const float*)d_in[5];
    const float* W2   = (const float*)d_in[6];
    float* out = (float*)d_out;

    float *h0, *h1;
    cudaGetSymbolAddress((void**)&h0, g_h0);
    cudaGetSymbolAddress((void**)&h1, g_h1);
    __nv_bfloat16 *whi, *wlo;
    cudaGetSymbolAddress((void**)&whi, g_Whi);
    cudaGetSymbolAddress((void**)&wlo, g_Wlo);

    cudaFuncSetAttribute(gemm_mma_kernel<false>,
                         cudaFuncAttributeMaxDynamicSharedMemorySize, MG_TOTAL);
    cudaFuncSetAttribute(gemm_mma_kernel<true>,
                         cudaFuncAttributeMaxDynamicSharedMemorySize, MG_TOTAL);

    // weight split conversion + CSR build (independent of GEMM0)
    convert_w_kernel<<<(W_TOTAL + 255) / 256, 256>>>(W0, W1, W2);
    zero_counts_kernel<<<(N_NODES + 255) / 256, 256>>>();
    hist_kernel<<<(N_EDGES + 255) / 256, 256>>>(erow);
    scan1_kernel<<<SCAN_BLOCKS, 1024>>>();
    scan2_kernel<<<1, 128>>>();
    scan3_kernel<<<SCAN_BLOCKS, 1024>>>();
    scatter_kernel<<<(N_EDGES + 255) / 256, 256>>>(erow, ecol, eval);

    const int mtiles = (N_NODES + 127) / 128;
    // h0 = x @ W0^T
    gemm_mma_kernel<false><<<dim3(4, mtiles), 512, MG_TOTAL>>>(
        x, whi, wlo, h0, N_NODES, D_HID);
    // h1 = relu(A @ h0), 4 feature-chunk passes for L2 residency
    for (int chunk = 0; chunk < 4; chunk++)
        spmm_relu_chunk_kernel<<<(N_NODES * 32 + 255) / 256, 256>>>(chunk);
    // h0 = relu(h1 @ W1^T)
    gemm_mma_kernel<true><<<dim3(4, mtiles), 512, MG_TOTAL>>>(
        h1, whi + 262144, wlo + 262144, h0, N_NODES, D_HID);
    // out = h0 @ W2^T
    gemm_mma_kernel<false><<<dim3(2, mtiles), 512, MG_TOTAL>>>(
        h0, whi + 524288, wlo + 524288, out, N_NODES, D_OUT);
}